// round 14
// baseline (speedup 1.0000x reference)
#include <cuda_runtime.h>
#include <cstdint>
#include <climits>

// Problem constants
#define BSZ   4096
#define CDIM  128
#define NSUP  32768          // 4096*8 support rows
#define PIDS  256
#define BLKC  128            // support columns per identity block
#define NSPLIT 8
#define BPS   (PIDS/NSPLIT)  // 32 blocks per split
#define MTILE 128
#define MTILES (BSZ/MTILE)   // 32
#define INV_TEMP 20.0f
#define EPSV 1e-6f
#define SROWB 144            // smem row stride in bytes for int8 tiles (128+16 pad)
#define TILEB 16384          // 128x128 int8 block tile bytes (dense, row-major)

// Scratch (static device globals)
__device__ int8_t g_fs_i8[(size_t)NSUP * CDIM];          // 4 MB (L2-resident)
__device__ int g_maxA;     // float bits of max|feats|   (atomicMax-idempotent)
__device__ int g_maxB;     // float bits of max|feats_s|
__device__ float g_negpart[NSPLIT * BSZ];
__device__ float g_pospart[NSPLIT * BSZ];

// ---------------------------------------------------------------------------
// Kernel 0: abs-max of feats (blocks 0..255) and feats_s (blocks 256..2303)
// atomicMax on float-bit ints (nonneg floats order-isomorphic). Idempotent
// across graph replays -> deterministic.
// ---------------------------------------------------------------------------
__global__ void k_absmax(const float* __restrict__ fa, const float* __restrict__ fb) {
    const int b = blockIdx.x;
    const float* src;
    int* dst;
    size_t base;
    if (b < 256) { src = fa; dst = &g_maxA; base = (size_t)b * 2048; }
    else         { src = fb; dst = &g_maxB; base = (size_t)(b - 256) * 2048; }
    const float4* p = (const float4*)(src + base) + threadIdx.x * 2;
    float4 v0 = p[0], v1 = p[1];
    float m = fmaxf(fmaxf(fmaxf(fabsf(v0.x), fabsf(v0.y)), fmaxf(fabsf(v0.z), fabsf(v0.w))),
                    fmaxf(fmaxf(fabsf(v1.x), fabsf(v1.y)), fmaxf(fabsf(v1.z), fabsf(v1.w))));
#pragma unroll
    for (int o = 16; o > 0; o >>= 1)
        m = fmaxf(m, __shfl_xor_sync(0xFFFFFFFFu, m, o));
    if ((threadIdx.x & 31) == 0) atomicMax(dst, __float_as_int(m));
}

// ---------------------------------------------------------------------------
// Kernel 1: quantize feats_s fp32 -> int8 with global scale 127/maxB.
// 16 elements per thread.
// ---------------------------------------------------------------------------
__global__ void k_quant(const float* __restrict__ fs) {
    const float inv = 127.0f / __int_as_float(g_maxB);
    const size_t i = ((size_t)blockIdx.x * blockDim.x + threadIdx.x) * 16;
    const float4* p = (const float4*)(fs + i);
    uint32_t w[4];
#pragma unroll
    for (int k = 0; k < 4; k++) {
        float4 v = p[k];
        int r0 = __float2int_rn(v.x * inv);
        int r1 = __float2int_rn(v.y * inv);
        int r2 = __float2int_rn(v.z * inv);
        int r3 = __float2int_rn(v.w * inv);
        w[k] = (uint32_t)(r0 & 255) | ((uint32_t)(r1 & 255) << 8) |
               ((uint32_t)(r2 & 255) << 16) | ((uint32_t)(r3 & 255) << 24);
    }
    *(uint4*)(g_fs_i8 + i) = make_uint4(w[0], w[1], w[2], w[3]);
}

// ---------------------------------------------------------------------------
// Helpers
// ---------------------------------------------------------------------------
__device__ __forceinline__ void cp_async16(uint32_t smem_addr, const void* gptr) {
    asm volatile("cp.async.cg.shared.global [%0], [%1], 16;\n"
                 :: "r"(smem_addr), "l"(gptr));
}
__device__ __forceinline__ void cp_commit() { asm volatile("cp.async.commit_group;\n"); }
template <int N> __device__ __forceinline__ void cp_wait() {
    asm volatile("cp.async.wait_group %0;\n" :: "n"(N));
}

// s8 x s8 -> s32, m16n8k32
__device__ __forceinline__ void mma_s8(int* d, const uint32_t* a, uint32_t b0, uint32_t b1) {
    asm volatile(
        "mma.sync.aligned.m16n8k32.row.col.s32.s8.s8.s32 "
        "{%0,%1,%2,%3}, {%4,%5,%6,%7}, {%8,%9}, {%0,%1,%2,%3};\n"
        : "+r"(d[0]), "+r"(d[1]), "+r"(d[2]), "+r"(d[3])
        : "r"(a[0]), "r"(a[1]), "r"(a[2]), "r"(a[3]), "r"(b0), "r"(b1));
}

// ---------------------------------------------------------------------------
// Kernel 2: int8 tiled MMA + segmented int min/max (R4 two-barrier skeleton).
// grid (MTILES, NSPLIT) = 256 CTAs, 256 threads, 2 CTAs/SM.
// Warps: 4 along M (32 rows each) x 2 along N (64 cols each).
// Single N pass: acc int[2][8][4] (64 regs) + A frags (32 regs).
// ---------------------------------------------------------------------------
extern __shared__ char smem_raw[];

__global__ __launch_bounds__(256, 2) void k_main(const float* __restrict__ feats) {
    int8_t* sA = (int8_t*)smem_raw;                       // 128 x SROWB = 18432
    int8_t* sB = sA + MTILE * SROWB;                      // 2 x 128 x SROWB = 36864
    int* sMax = (int*)(sB + 2 * BLKC * SROWB);            // [128][2]
    int* sMin = sMax + MTILE * 2;                         // [128][2]

    const int tid  = threadIdx.x;
    const int wid  = tid >> 5;
    const int lane = tid & 31;
    const int wm   = wid & 3;       // warp row (0..3)
    const int wn   = wid >> 2;      // warp col (0..1)
    const int g    = lane >> 2;
    const int q    = lane & 3;
    const int mtile = blockIdx.x;
    const int m0   = mtile * MTILE;
    const int split = blockIdx.y;
    const int jbase = split * BPS;
    const int own_j0 = mtile * 8;   // this mtile's identities: [own_j0, own_j0+8)

    auto issueB = [&](int j, int buf) {
        const char* src = (const char*)(g_fs_i8 + (size_t)j * TILEB);
        int8_t* dstb = sB + buf * BLKC * SROWB;
        #pragma unroll
        for (int it = 0; it < 4; it++) {
            int idx = tid + it * 256;                // 0..1023 (16B chunks)
            int r = idx >> 3, ch = idx & 7;
            uint32_t da = (uint32_t)__cvta_generic_to_shared(dstb + r * SROWB + ch * 16);
            cp_async16(da, src + (size_t)idx * 16);
        }
        cp_commit();
    };
    issueB(jbase, 0);

    // Quantize A tile fp32 -> int8 into smem (global scale 127/maxA)
    const float maxA = __int_as_float(g_maxA);
    const float maxB = __int_as_float(g_maxB);
    const float invA = 127.0f / maxA;
    const float C = maxA * maxB * (INV_TEMP / (127.0f * 127.0f));   // sim*20 = C*dot_int
    for (int idx = tid; idx < MTILE * CDIM; idx += 256) {
        int r = idx >> 7, c = idx & 127;
        int v = __float2int_rn(feats[(size_t)(m0 + r) * CDIM + c] * invA);
        sA[r * SROWB + c] = (int8_t)v;
    }
    __syncthreads();

    // Preload A fragments: 32 rows x K=128 per warp (mi2 x ks4 x 4 = 32 regs)
    uint32_t afr[2][4][4];
#pragma unroll
    for (int mi = 0; mi < 2; mi++) {
        const int rm0 = 32 * wm + 16 * mi + g;
#pragma unroll
        for (int ks = 0; ks < 4; ks++) {
            const int c0 = 32 * ks + 4 * q;
            afr[mi][ks][0] = *(const uint32_t*)(sA + rm0 * SROWB + c0);
            afr[mi][ks][1] = *(const uint32_t*)(sA + (rm0 + 8) * SROWB + c0);
            afr[mi][ks][2] = *(const uint32_t*)(sA + rm0 * SROWB + c0 + 16);
            afr[mi][ks][3] = *(const uint32_t*)(sA + (rm0 + 8) * SROWB + c0 + 16);
        }
    }

    // Per-warp B base byte offset: row (64wn + g), col 4q. ni adds 8*SROWB rows.
    const int bbase_off = (64 * wn + g) * SROWB + 4 * q;

    float negacc = 0.0f;
    float posval = 0.0f;

    for (int jb = 0; jb < BPS; ++jb) {
        const int j   = jbase + jb;
        const int buf = jb & 1;
        const bool ownIter = (unsigned)(j - own_j0) < 8u;   // uniform predicate

        if (jb + 1 < BPS) { issueB(j + 1, buf ^ 1); cp_wait<1>(); }
        else              { cp_wait<0>(); }
        __syncthreads();

        const int8_t* bb = sB + buf * BLKC * SROWB + bbase_off;

        int acc[2][8][4];
#pragma unroll
        for (int mi = 0; mi < 2; mi++)
#pragma unroll
            for (int ni = 0; ni < 8; ni++)
#pragma unroll
                for (int cc = 0; cc < 4; cc++) acc[mi][ni][cc] = 0;

#pragma unroll
        for (int ks = 0; ks < 4; ks++) {
            const int kc = 32 * ks;
#pragma unroll
            for (int ni = 0; ni < 8; ni++) {
                const int8_t* bp = bb + ni * 8 * SROWB + kc;
                uint32_t b0 = *(const uint32_t*)(bp);
                uint32_t b1 = *(const uint32_t*)(bp + 16);
                mma_s8(acc[0][ni], afr[0][ks], b0, b1);
                mma_s8(acc[1][ni], afr[1][ks], b0, b1);
            }
        }

        // Epilogue: int max fold (always); min only on own-iters
#pragma unroll
        for (int mi = 0; mi < 2; mi++) {
#pragma unroll
            for (int h = 0; h < 2; h++) {
                int mx = INT_MIN;
#pragma unroll
                for (int ni = 0; ni < 8; ni++)
                    mx = max(mx, max(acc[mi][ni][2 * h], acc[mi][ni][2 * h + 1]));
                mx = max(mx, __shfl_xor_sync(0xFFFFFFFFu, mx, 1));
                mx = max(mx, __shfl_xor_sync(0xFFFFFFFFu, mx, 2));
                if (q == 0) {
                    int row = 32 * wm + 16 * mi + 8 * h + g;
                    sMax[row * 2 + wn] = mx;
                }
            }
        }
        if (ownIter) {
#pragma unroll
            for (int mi = 0; mi < 2; mi++) {
#pragma unroll
                for (int h = 0; h < 2; h++) {
                    int mn = INT_MAX;
#pragma unroll
                    for (int ni = 0; ni < 8; ni++)
                        mn = min(mn, min(acc[mi][ni][2 * h], acc[mi][ni][2 * h + 1]));
                    mn = min(mn, __shfl_xor_sync(0xFFFFFFFFu, mn, 1));
                    mn = min(mn, __shfl_xor_sync(0xFFFFFFFFu, mn, 2));
                    if (q == 0) {
                        int row = 32 * wm + 16 * mi + 8 * h + g;
                        sMin[row * 2 + wn] = mn;
                    }
                }
            }
        }
        __syncthreads();

        if (tid < MTILE) {
            const int anchor = m0 + tid;
            if ((anchor >> 4) == j) {
                int mn = min(sMin[tid * 2], sMin[tid * 2 + 1]);
                posval = __expf((float)mn * C);        // min of exp == exp of min
            } else {
                int mx = max(sMax[tid * 2], sMax[tid * 2 + 1]);
                negacc += __expf((float)mx * C);       // max of exp == exp of max
            }
        }
        // loop-top sync protects sMax/sMin & sB reuse
    }

    if (tid < MTILE) {
        g_negpart[split * BSZ + m0 + tid] = negacc;
        g_pospart[split * BSZ + m0 + tid] = posval;    // 0.0 for non-own splits
    }
}

// ---------------------------------------------------------------------------
// Kernel 3: combine splits, per-anchor loss, deterministic mean
// ---------------------------------------------------------------------------
__global__ void k_final(float* __restrict__ out) {
    __shared__ double red[256];
    int tid = threadIdx.x;
    double s = 0.0;
    for (int a = tid; a < BSZ; a += 256) {
        float neg = 0.0f, pos = 0.0f;
#pragma unroll
        for (int sp = 0; sp < NSPLIT; sp++) {
            neg += g_negpart[sp * BSZ + a];
            pos += g_pospart[sp * BSZ + a];
        }
        float loss = -logf(pos / (pos + neg + EPSV) + EPSV);
        s += (double)loss;
    }
    red[tid] = s;
    __syncthreads();
    for (int o = 128; o > 0; o >>= 1) {
        if (tid < o) red[tid] += red[tid + o];
        __syncthreads();
    }
    if (tid == 0) out[0] = (float)(red[0] / (double)BSZ);
}

// ---------------------------------------------------------------------------
// Launch
// ---------------------------------------------------------------------------
extern "C" void kernel_launch(void* const* d_in, const int* in_sizes, int n_in,
                              void* d_out, int out_size) {
    const float* feats   = (const float*)d_in[0];   // [4096,128] fp32
    const float* feats_s = (const float*)d_in[1];   // [4096,8,128] fp32
    float* out = (float*)d_out;

    // A (18432) + 2xB (36864) + int min/max (2048) = 57344 B; 2 CTAs/SM easily
    const int smem_bytes = MTILE * SROWB + 2 * BLKC * SROWB + 2 * MTILE * 2 * 4;
    cudaFuncSetAttribute(k_main, cudaFuncAttributeMaxDynamicSharedMemorySize, smem_bytes);

    k_absmax<<<2304, 256>>>(feats, feats_s);        // 256 blocks feats, 2048 feats_s
    k_quant<<<(NSUP * CDIM / 16) / 256, 256>>>(feats_s);
    dim3 grid(MTILES, NSPLIT);
    k_main<<<grid, 256, smem_bytes>>>(feats);
    k_final<<<1, 256>>>(out);
}

// round 15
// speedup vs baseline: 2.6435x; 2.6435x over previous
#include <cuda_runtime.h>
#include <cuda_bf16.h>
#include <cstdint>

// Problem constants
#define BSZ   4096
#define CDIM  128
#define NSUP  32768          // 4096*8 support rows
#define PIDS  256
#define BLKC  128            // support columns per identity block
#define NSPLIT 8
#define BPS   (PIDS/NSPLIT)  // 32 blocks per split
#define MTILE 128
#define MTILES (BSZ/MTILE)   // 32
#define INV_TEMP 20.0f
#define EPSV 1e-6f
#define SROW 136             // smem row stride in bf16 (128+8 pad, conflict-free)

// Scratch (static device globals)
__device__ __nv_bfloat16 g_fs_bf[(size_t)NSUP * CDIM];   // 8 MB (L2-resident)
__device__ float g_negpart[NSPLIT * BSZ];
__device__ float g_pospart[NSPLIT * BSZ];

// ---------------------------------------------------------------------------
// Kernel 1: convert feats_s fp32 -> bf16 (2 float4 per thread)
// ---------------------------------------------------------------------------
__global__ void k_convert(const float* __restrict__ fs) {
    int i = (blockIdx.x * blockDim.x + threadIdx.x) * 2;    // float4 index
    float4 v0 = ((const float4*)fs)[i];
    float4 v1 = ((const float4*)fs)[i + 1];
    __nv_bfloat162* dst = (__nv_bfloat162*)g_fs_bf;
    dst[2 * i]     = __floats2bfloat162_rn(v0.x, v0.y);
    dst[2 * i + 1] = __floats2bfloat162_rn(v0.z, v0.w);
    dst[2 * i + 2] = __floats2bfloat162_rn(v1.x, v1.y);
    dst[2 * i + 3] = __floats2bfloat162_rn(v1.z, v1.w);
}

// ---------------------------------------------------------------------------
// Helpers
// ---------------------------------------------------------------------------
__device__ __forceinline__ void cp_async16(uint32_t smem_addr, const void* gptr) {
    asm volatile("cp.async.cg.shared.global [%0], [%1], 16;\n"
                 :: "r"(smem_addr), "l"(gptr));
}
__device__ __forceinline__ void cp_commit() { asm volatile("cp.async.commit_group;\n"); }
template <int N> __device__ __forceinline__ void cp_wait() {
    asm volatile("cp.async.wait_group %0;\n" :: "n"(N));
}

__device__ __forceinline__ void mma16816(float* d, const uint32_t* a, uint32_t b0, uint32_t b1) {
    asm volatile(
        "mma.sync.aligned.m16n8k16.row.col.f32.bf16.bf16.f32 "
        "{%0,%1,%2,%3}, {%4,%5,%6,%7}, {%8,%9}, {%0,%1,%2,%3};\n"
        : "+f"(d[0]), "+f"(d[1]), "+f"(d[2]), "+f"(d[3])
        : "r"(a[0]), "r"(a[1]), "r"(a[2]), "r"(a[3]), "r"(b0), "r"(b1));
}

__device__ __forceinline__ void ldmatrix_x4(uint32_t& r0, uint32_t& r1, uint32_t& r2, uint32_t& r3,
                                            uint32_t addr) {
    asm volatile("ldmatrix.sync.aligned.m8n8.x4.shared.b16 {%0,%1,%2,%3}, [%4];"
                 : "=r"(r0), "=r"(r1), "=r"(r2), "=r"(r3) : "r"(addr));
}

// ---------------------------------------------------------------------------
// Kernel 2: tiled bf16 MMA + per-identity-block min/max reduction.
// grid (MTILES, NSPLIT) = 256 CTAs, 256 threads, 2 CTAs/SM.
// Warps: 4 along M x 2 along N; N accumulated in two 64-col passes.
// B fragments via ldmatrix.x4 (32 instr/warp-iter vs 256 LDS.32).
// ---------------------------------------------------------------------------
extern __shared__ char smem_raw[];

__global__ __launch_bounds__(256, 2) void k_main(const float* __restrict__ feats) {
    __nv_bfloat16* sA = (__nv_bfloat16*)smem_raw;                  // MTILE x SROW
    __nv_bfloat16* sB = sA + MTILE * SROW;                         // 2 x BLKC x SROW
    float* sMax = (float*)(sB + 2 * BLKC * SROW);                  // MTILE x 2
    float* sMin = sMax + MTILE * 2;                                // MTILE x 2

    const int tid  = threadIdx.x;
    const int wid  = tid >> 5;
    const int lane = tid & 31;
    const int wm   = wid & 3;       // warp row (0..3)
    const int wn   = wid >> 2;      // warp col (0..1)
    const int g    = lane >> 2;
    const int q    = lane & 3;
    const int mtile = blockIdx.x;
    const int m0   = mtile * MTILE;
    const int split = blockIdx.y;
    const int jbase = split * BPS;

    auto issueB = [&](int j, int buf) {
        const char* src = (const char*)(g_fs_bf + (size_t)j * BLKC * CDIM);
        __nv_bfloat16* dstb = sB + buf * BLKC * SROW;
        #pragma unroll
        for (int it = 0; it < 8; it++) {
            int idx = tid + it * 256;                // 0..2047
            int r = idx >> 4, ch = idx & 15;
            uint32_t da = (uint32_t)__cvta_generic_to_shared(dstb + r * SROW + ch * 8);
            cp_async16(da, src + (size_t)idx * 16);
        }
        cp_commit();
    };
    issueB(jbase, 0);

    // feats tile -> bf16 smem
    for (int idx = tid; idx < MTILE * CDIM; idx += 256) {
        int r = idx >> 7, c = idx & 127;
        sA[r * SROW + c] = __float2bfloat16(feats[(size_t)(m0 + r) * CDIM + c]);
    }
    __syncthreads();

    // Preload A fragments: 32 rows x K=128 per warp (64 regs)
    uint32_t afr[2][8][4];
    {
        const int row_off = lane & 15;
        const int col_off = 8 * (lane >> 4);
#pragma unroll
        for (int mi = 0; mi < 2; mi++) {
            const int rm = 32 * wm + 16 * mi + row_off;
#pragma unroll
            for (int ks = 0; ks < 8; ks++) {
                uint32_t addr = (uint32_t)__cvta_generic_to_shared(&sA[rm * SROW + 16 * ks + col_off]);
                asm volatile("ldmatrix.sync.aligned.m8n8.x4.shared.b16 {%0,%1,%2,%3}, [%4];"
                             : "=r"(afr[mi][ks][0]), "=r"(afr[mi][ks][1]),
                               "=r"(afr[mi][ks][2]), "=r"(afr[mi][ks][3])
                             : "r"(addr));
            }
        }
    }

    // Per-lane ldmatrix.x4 base address for B fragments.
    // Matrices per load: [ni_lo,k0][ni_lo,k8][ni_hi,k0][ni_hi,k8]
    // lanes 0-7 -> m0 rows, 8-15 -> m1, 16-23 -> m2, 24-31 -> m3.
    const int sel  = lane >> 3;            // 0..3
    const int rrow = lane & 7;
    const int b_nrow  = 64 * wn + (sel >> 1) * 8 + rrow;   // ni_hi adds +8 later via loop offset
    const int b_khalf = (sel & 1) * 8;
    const uint32_t b_lane_base =
        (uint32_t)__cvta_generic_to_shared(sB) + 2u * (uint32_t)(b_nrow * SROW + b_khalf);

    float negacc = 0.0f;
    float posval = 0.0f;

    for (int jb = 0; jb < BPS; ++jb) {
        const int buf = jb & 1;
        if (jb + 1 < BPS) { issueB(jbase + jb + 1, buf ^ 1); cp_wait<1>(); }
        else              { cp_wait<0>(); }
        __syncthreads();

        const uint32_t blm = b_lane_base + (uint32_t)(buf * BLKC * SROW * 2);

        float vmx[2][2], vmn[2][2];
#pragma unroll
        for (int p = 0; p < 2; p++) {          // two 64-col N passes (reg pressure)
            float acc[2][4][4];
#pragma unroll
            for (int mi = 0; mi < 2; mi++)
#pragma unroll
                for (int n4 = 0; n4 < 4; n4++)
#pragma unroll
                    for (int cc = 0; cc < 4; cc++) acc[mi][n4][cc] = 0.0f;

#pragma unroll
            for (int ks = 0; ks < 8; ks++) {
#pragma unroll
                for (int np = 0; np < 2; np++) {      // ni pair: ni = 4p+2np (+0/+1)
                    uint32_t r0, r1, r2, r3;
                    uint32_t a = blm + 2u * (uint32_t)(((4 * p + 2 * np) * 8) * SROW + 16 * ks);
                    ldmatrix_x4(r0, r1, r2, r3, a);
                    mma16816(acc[0][2 * np],     afr[0][ks], r0, r1);
                    mma16816(acc[1][2 * np],     afr[1][ks], r0, r1);
                    mma16816(acc[0][2 * np + 1], afr[0][ks], r2, r3);
                    mma16816(acc[1][2 * np + 1], afr[1][ks], r2, r3);
                }
            }
            // fold this pass's 8 col-values per row into running partials
#pragma unroll
            for (int mi = 0; mi < 2; mi++) {
#pragma unroll
                for (int h = 0; h < 2; h++) {
                    float mx = -1e30f, mn = 1e30f;
#pragma unroll
                    for (int n4 = 0; n4 < 4; n4++) {
                        float c0 = acc[mi][n4][2 * h];
                        float c1 = acc[mi][n4][2 * h + 1];
                        mx = fmaxf(mx, fmaxf(c0, c1));
                        mn = fminf(mn, fminf(c0, c1));
                    }
                    if (p == 0) { vmx[mi][h] = mx; vmn[mi][h] = mn; }
                    else { vmx[mi][h] = fmaxf(vmx[mi][h], mx); vmn[mi][h] = fminf(vmn[mi][h], mn); }
                }
            }
        }

        // cross-lane (q) reduce + smem
#pragma unroll
        for (int mi = 0; mi < 2; mi++) {
#pragma unroll
            for (int h = 0; h < 2; h++) {
                float mx = vmx[mi][h], mn = vmn[mi][h];
                mx = fmaxf(mx, __shfl_xor_sync(0xFFFFFFFFu, mx, 1));
                mx = fmaxf(mx, __shfl_xor_sync(0xFFFFFFFFu, mx, 2));
                mn = fminf(mn, __shfl_xor_sync(0xFFFFFFFFu, mn, 1));
                mn = fminf(mn, __shfl_xor_sync(0xFFFFFFFFu, mn, 2));
                if (q == 0) {
                    int row = 32 * wm + 16 * mi + 8 * h + g;
                    sMax[row * 2 + wn] = mx;
                    sMin[row * 2 + wn] = mn;
                }
            }
        }
        __syncthreads();

        if (tid < MTILE) {
            float mx = fmaxf(sMax[tid * 2], sMax[tid * 2 + 1]);
            float mn = fminf(sMin[tid * 2], sMin[tid * 2 + 1]);
            int anchor = m0 + tid;
            if ((anchor >> 4) == (jbase + jb))       // own identity block
                posval = expf(mn * INV_TEMP);        // min of exp == exp of min
            else
                negacc += expf(mx * INV_TEMP);       // max of exp == exp of max
        }
        // next iter's wait+syncthreads orders sMax reads vs. rewrites
    }

    if (tid < MTILE) {
        g_negpart[split * BSZ + m0 + tid] = negacc;
        g_pospart[split * BSZ + m0 + tid] = posval;
    }
}

// ---------------------------------------------------------------------------
// Kernel 3: combine splits, per-anchor loss, deterministic mean
// ---------------------------------------------------------------------------
__global__ void k_final(float* __restrict__ out) {
    __shared__ double red[256];
    int tid = threadIdx.x;
    double s = 0.0;
    for (int a = tid; a < BSZ; a += 256) {
        float neg = 0.0f, pos = 0.0f;
#pragma unroll
        for (int sp = 0; sp < NSPLIT; sp++) {
            neg += g_negpart[sp * BSZ + a];
            pos += g_pospart[sp * BSZ + a];
        }
        float loss = -logf(pos / (pos + neg + EPSV) + EPSV);
        s += (double)loss;
    }
    red[tid] = s;
    __syncthreads();
    for (int o = 128; o > 0; o >>= 1) {
        if (tid < o) red[tid] += red[tid + o];
        __syncthreads();
    }
    if (tid == 0) out[0] = (float)(red[0] / (double)BSZ);
}

// ---------------------------------------------------------------------------
// Launch
// ---------------------------------------------------------------------------
extern "C" void kernel_launch(void* const* d_in, const int* in_sizes, int n_in,
                              void* d_out, int out_size) {
    const float* feats   = (const float*)d_in[0];   // [4096,128] fp32
    const float* feats_s = (const float*)d_in[1];   // [4096,8,128] fp32
    float* out = (float*)d_out;

    // A (34816) + 2xB (69632) + reduce scratch (2048) = 106496 B; 2 CTAs/SM
    const int smem_bytes = MTILE * SROW * 2 + 2 * BLKC * SROW * 2 + MTILE * 2 * 4 * 2;
    cudaFuncSetAttribute(k_main, cudaFuncAttributeMaxDynamicSharedMemorySize, smem_bytes);

    k_convert<<<(NSUP * CDIM / 8) / 256, 256>>>(feats_s);
    dim3 grid(MTILES, NSPLIT);
    k_main<<<grid, 256, smem_bytes>>>(feats);
    k_final<<<1, 256>>>(out);
}

// round 16
// speedup vs baseline: 2.7930x; 1.0566x over previous
#include <cuda_runtime.h>
#include <cuda_bf16.h>
#include <cstdint>

// Problem constants
#define BSZ   4096
#define CDIM  128
#define NSUP  32768          // 4096*8 support rows
#define PIDS  256
#define BLKC  128            // support columns per identity block
#define NSPLIT 32
#define BPS   (PIDS/NSPLIT)  // 8 blocks per split
#define MTILE 128
#define MTILES (BSZ/MTILE)   // 32
#define INV_TEMP 20.0f
#define EPSV 1e-6f
#define SROW 136             // smem row stride in bf16 (128+8 pad, conflict-free)

// Scratch (static device globals)
__device__ __nv_bfloat16 g_fs_bf[(size_t)NSUP * CDIM];   // 8 MB (L2-resident)
__device__ float g_negpart[NSPLIT * BSZ];                // 512 KB
__device__ float g_pospart[NSPLIT * BSZ];
__device__ double g_losspart[32];

// ---------------------------------------------------------------------------
// Kernel 1: convert feats_s fp32 -> bf16 (4 float4 per thread, MLP=4)
// ---------------------------------------------------------------------------
__global__ void k_convert(const float* __restrict__ fs) {
    int i = (blockIdx.x * blockDim.x + threadIdx.x) * 4;    // float4 index
    float4 v0 = ((const float4*)fs)[i];
    float4 v1 = ((const float4*)fs)[i + 1];
    float4 v2 = ((const float4*)fs)[i + 2];
    float4 v3 = ((const float4*)fs)[i + 3];
    __nv_bfloat162* dst = (__nv_bfloat162*)g_fs_bf;
    dst[2 * i]     = __floats2bfloat162_rn(v0.x, v0.y);
    dst[2 * i + 1] = __floats2bfloat162_rn(v0.z, v0.w);
    dst[2 * i + 2] = __floats2bfloat162_rn(v1.x, v1.y);
    dst[2 * i + 3] = __floats2bfloat162_rn(v1.z, v1.w);
    dst[2 * i + 4] = __floats2bfloat162_rn(v2.x, v2.y);
    dst[2 * i + 5] = __floats2bfloat162_rn(v2.z, v2.w);
    dst[2 * i + 6] = __floats2bfloat162_rn(v3.x, v3.y);
    dst[2 * i + 7] = __floats2bfloat162_rn(v3.z, v3.w);
}

// ---------------------------------------------------------------------------
// Helpers
// ---------------------------------------------------------------------------
__device__ __forceinline__ void cp_async16(uint32_t smem_addr, const void* gptr) {
    asm volatile("cp.async.cg.shared.global [%0], [%1], 16;\n"
                 :: "r"(smem_addr), "l"(gptr));
}
__device__ __forceinline__ void cp_commit() { asm volatile("cp.async.commit_group;\n"); }
template <int N> __device__ __forceinline__ void cp_wait() {
    asm volatile("cp.async.wait_group %0;\n" :: "n"(N));
}

__device__ __forceinline__ void mma16816(float* d, const uint32_t* a, uint32_t b0, uint32_t b1) {
    asm volatile(
        "mma.sync.aligned.m16n8k16.row.col.f32.bf16.bf16.f32 "
        "{%0,%1,%2,%3}, {%4,%5,%6,%7}, {%8,%9}, {%0,%1,%2,%3};\n"
        : "+f"(d[0]), "+f"(d[1]), "+f"(d[2]), "+f"(d[3])
        : "r"(a[0]), "r"(a[1]), "r"(a[2]), "r"(a[3]), "r"(b0), "r"(b1));
}

// ---------------------------------------------------------------------------
// Kernel 2: tiled bf16 MMA + per-identity-block min/max reduction (R4 body).
// grid (MTILES, NSPLIT) = 1024 CTAs, 256 threads, 2 CTAs/SM.
// BPS=8 iters/CTA -> near-perfect SM load balance (max ~56 vs ideal 55.4).
// ---------------------------------------------------------------------------
extern __shared__ char smem_raw[];

__global__ __launch_bounds__(256, 2) void k_main(const float* __restrict__ feats) {
    __nv_bfloat16* sA = (__nv_bfloat16*)smem_raw;                  // MTILE x SROW
    __nv_bfloat16* sB = sA + MTILE * SROW;                         // 2 x BLKC x SROW
    float* sMax = (float*)(sB + 2 * BLKC * SROW);                  // MTILE x 2
    float* sMin = sMax + MTILE * 2;                                // MTILE x 2

    const int tid  = threadIdx.x;
    const int wid  = tid >> 5;
    const int lane = tid & 31;
    const int wm   = wid & 3;       // warp row (0..3)
    const int wn   = wid >> 2;      // warp col (0..1)
    const int g    = lane >> 2;
    const int q    = lane & 3;
    const int m0   = blockIdx.x * MTILE;
    const int split = blockIdx.y;
    const int jbase = split * BPS;

    auto issueB = [&](int j, int buf) {
        const char* src = (const char*)(g_fs_bf + (size_t)j * BLKC * CDIM);
        __nv_bfloat16* dstb = sB + buf * BLKC * SROW;
        #pragma unroll
        for (int it = 0; it < 8; it++) {
            int idx = tid + it * 256;                // 0..2047
            int r = idx >> 4, ch = idx & 15;
            uint32_t da = (uint32_t)__cvta_generic_to_shared(dstb + r * SROW + ch * 8);
            cp_async16(da, src + (size_t)idx * 16);
        }
        cp_commit();
    };
    issueB(jbase, 0);

    // feats tile -> bf16 smem
    for (int idx = tid; idx < MTILE * CDIM; idx += 256) {
        int r = idx >> 7, c = idx & 127;
        sA[r * SROW + c] = __float2bfloat16(feats[(size_t)(m0 + r) * CDIM + c]);
    }
    __syncthreads();

    // Preload A fragments: 32 rows x K=128 per warp (64 regs)
    uint32_t afr[2][8][4];
    {
        const int row_off = lane & 15;
        const int col_off = 8 * (lane >> 4);
#pragma unroll
        for (int mi = 0; mi < 2; mi++) {
            const int rm = 32 * wm + 16 * mi + row_off;
#pragma unroll
            for (int ks = 0; ks < 8; ks++) {
                uint32_t addr = (uint32_t)__cvta_generic_to_shared(&sA[rm * SROW + 16 * ks + col_off]);
                asm volatile("ldmatrix.sync.aligned.m8n8.x4.shared.b16 {%0,%1,%2,%3}, [%4];"
                             : "=r"(afr[mi][ks][0]), "=r"(afr[mi][ks][1]),
                               "=r"(afr[mi][ks][2]), "=r"(afr[mi][ks][3])
                             : "r"(addr));
            }
        }
    }

    // B fragment offsets (bf16 elements): conflict-free (word = 4g+q mod 32)
    uint32_t boff[8];
#pragma unroll
    for (int ni = 0; ni < 8; ni++)
        boff[ni] = (uint32_t)((64 * wn + 8 * ni + g) * SROW + 2 * q);

    float negacc = 0.0f;
    float posval = 0.0f;

    for (int jb = 0; jb < BPS; ++jb) {
        const int buf = jb & 1;
        if (jb + 1 < BPS) { issueB(jbase + jb + 1, buf ^ 1); cp_wait<1>(); }
        else              { cp_wait<0>(); }
        __syncthreads();

        const __nv_bfloat16* bbase = sB + buf * BLKC * SROW;

        float vmx[2][2], vmn[2][2];
#pragma unroll
        for (int p = 0; p < 2; p++) {          // two 64-col N passes (reg pressure)
            float acc[2][4][4];
#pragma unroll
            for (int mi = 0; mi < 2; mi++)
#pragma unroll
                for (int n4 = 0; n4 < 4; n4++)
#pragma unroll
                    for (int cc = 0; cc < 4; cc++) acc[mi][n4][cc] = 0.0f;

#pragma unroll
            for (int ks = 0; ks < 8; ks++) {
                const int kc = 16 * ks;
#pragma unroll
                for (int n4 = 0; n4 < 4; n4++) {
                    const __nv_bfloat16* bp = bbase + boff[4 * p + n4];
                    uint32_t b0 = *(const uint32_t*)(bp + kc);
                    uint32_t b1 = *(const uint32_t*)(bp + kc + 8);
                    mma16816(acc[0][n4], afr[0][ks], b0, b1);
                    mma16816(acc[1][n4], afr[1][ks], b0, b1);
                }
            }
            // fold this pass's 8 col-values per row into running partials
#pragma unroll
            for (int mi = 0; mi < 2; mi++) {
#pragma unroll
                for (int h = 0; h < 2; h++) {
                    float mx = -1e30f, mn = 1e30f;
#pragma unroll
                    for (int n4 = 0; n4 < 4; n4++) {
                        float c0 = acc[mi][n4][2 * h];
                        float c1 = acc[mi][n4][2 * h + 1];
                        mx = fmaxf(mx, fmaxf(c0, c1));
                        mn = fminf(mn, fminf(c0, c1));
                    }
                    if (p == 0) { vmx[mi][h] = mx; vmn[mi][h] = mn; }
                    else { vmx[mi][h] = fmaxf(vmx[mi][h], mx); vmn[mi][h] = fminf(vmn[mi][h], mn); }
                }
            }
        }

        // cross-lane (q) reduce + smem
#pragma unroll
        for (int mi = 0; mi < 2; mi++) {
#pragma unroll
            for (int h = 0; h < 2; h++) {
                float mx = vmx[mi][h], mn = vmn[mi][h];
                mx = fmaxf(mx, __shfl_xor_sync(0xFFFFFFFFu, mx, 1));
                mx = fmaxf(mx, __shfl_xor_sync(0xFFFFFFFFu, mx, 2));
                mn = fminf(mn, __shfl_xor_sync(0xFFFFFFFFu, mn, 1));
                mn = fminf(mn, __shfl_xor_sync(0xFFFFFFFFu, mn, 2));
                if (q == 0) {
                    int row = 32 * wm + 16 * mi + 8 * h + g;
                    sMax[row * 2 + wn] = mx;
                    sMin[row * 2 + wn] = mn;
                }
            }
        }
        __syncthreads();

        if (tid < MTILE) {
            float mx = fmaxf(sMax[tid * 2], sMax[tid * 2 + 1]);
            float mn = fminf(sMin[tid * 2], sMin[tid * 2 + 1]);
            int anchor = m0 + tid;
            if ((anchor >> 4) == (jbase + jb))       // own identity block
                posval = expf(mn * INV_TEMP);        // min of exp == exp of min
            else
                negacc += expf(mx * INV_TEMP);       // max of exp == exp of max
        }
        // next iter's wait+syncthreads orders sMax reads vs. rewrites
    }

    if (tid < MTILE) {
        g_negpart[split * BSZ + m0 + tid] = negacc;
        g_pospart[split * BSZ + m0 + tid] = posval;
    }
}

// ---------------------------------------------------------------------------
// Kernel 3a: per-anchor loss + per-CTA partial sum (32 CTAs x 128 threads)
// ---------------------------------------------------------------------------
__global__ void k_final_a() {
    __shared__ double red[128];
    const int tid = threadIdx.x;
    const int a = blockIdx.x * 128 + tid;
    float neg = 0.0f, pos = 0.0f;
#pragma unroll
    for (int sp = 0; sp < NSPLIT; sp++) {
        neg += g_negpart[sp * BSZ + a];
        pos += g_pospart[sp * BSZ + a];
    }
    float loss = -logf(pos / (pos + neg + EPSV) + EPSV);
    red[tid] = (double)loss;
    __syncthreads();
    for (int o = 64; o > 0; o >>= 1) {
        if (tid < o) red[tid] += red[tid + o];
        __syncthreads();
    }
    if (tid == 0) g_losspart[blockIdx.x] = red[0];
}

// ---------------------------------------------------------------------------
// Kernel 3b: combine 32 partials -> mean (1 warp, deterministic)
// ---------------------------------------------------------------------------
__global__ void k_final_b(float* __restrict__ out) {
    if (threadIdx.x == 0) {
        double s = 0.0;
        for (int i = 0; i < 32; i++) s += g_losspart[i];
        out[0] = (float)(s / (double)BSZ);
    }
}

// ---------------------------------------------------------------------------
// Launch
// ---------------------------------------------------------------------------
extern "C" void kernel_launch(void* const* d_in, const int* in_sizes, int n_in,
                              void* d_out, int out_size) {
    const float* feats   = (const float*)d_in[0];   // [4096,128] fp32
    const float* feats_s = (const float*)d_in[1];   // [4096,8,128] fp32
    float* out = (float*)d_out;

    // A (34816) + 2xB (69632) + reduce scratch (2048) = 106496 B; 2 CTAs/SM
    const int smem_bytes = MTILE * SROW * 2 + 2 * BLKC * SROW * 2 + MTILE * 2 * 4 * 2;
    cudaFuncSetAttribute(k_main, cudaFuncAttributeMaxDynamicSharedMemorySize, smem_bytes);

    k_convert<<<(NSUP * CDIM / 16) / 256, 256>>>(feats_s);
    dim3 grid(MTILES, NSPLIT);
    k_main<<<grid, 256, smem_bytes>>>(feats);
    k_final_a<<<32, 128>>>();
    k_final_b<<<1, 32>>>(out);
}

// round 17
// speedup vs baseline: 2.9422x; 1.0534x over previous
#include <cuda_runtime.h>
#include <cuda_bf16.h>
#include <cstdint>

// Problem constants
#define BSZ   4096
#define CDIM  128
#define NSUP  32768          // 4096*8 support rows
#define PIDS  256
#define BLKC  128            // support columns per identity block
#define NSPLIT 32
#define BPS   (PIDS/NSPLIT)  // 8 blocks per split
#define MTILE 128
#define MTILES (BSZ/MTILE)   // 32
#define INV_TEMP 20.0f
#define EPSV 1e-6f
#define SROW 136             // smem row stride in bf16 (128+8 pad, conflict-free)

// Scratch (static device globals)
__device__ __nv_bfloat16 g_fs_bf[(size_t)NSUP * CDIM];   // 8 MB (L2-resident)
__device__ __nv_bfloat16 g_f_bf[(size_t)BSZ * CDIM];     // 1 MB anchors, bf16
__device__ float g_negpart[NSPLIT * BSZ];                // 512 KB
__device__ float g_pospart[NSPLIT * BSZ];
__device__ double g_losspart[32];

// ---------------------------------------------------------------------------
// Kernel 1: convert feats_s AND feats fp32 -> bf16 (16 elements per thread).
// Linear element space: [0, NSUP*CDIM) -> g_fs_bf, then [.., +BSZ*CDIM) -> g_f_bf.
// ---------------------------------------------------------------------------
__global__ void k_convert(const float* __restrict__ fs, const float* __restrict__ fa) {
    int t = blockIdx.x * blockDim.x + threadIdx.x;
    const int nfs_t = (NSUP * CDIM) / 16;                 // threads for feats_s
    const float4* src;
    __nv_bfloat162* dst;
    int local;
    if (t < nfs_t) { src = (const float4*)fs; dst = (__nv_bfloat162*)g_fs_bf; local = t; }
    else           { src = (const float4*)fa; dst = (__nv_bfloat162*)g_f_bf;  local = t - nfs_t; }
    int i = local * 4;                                    // float4 index
    float4 v0 = src[i], v1 = src[i + 1], v2 = src[i + 2], v3 = src[i + 3];
    dst[2 * i]     = __floats2bfloat162_rn(v0.x, v0.y);
    dst[2 * i + 1] = __floats2bfloat162_rn(v0.z, v0.w);
    dst[2 * i + 2] = __floats2bfloat162_rn(v1.x, v1.y);
    dst[2 * i + 3] = __floats2bfloat162_rn(v1.z, v1.w);
    dst[2 * i + 4] = __floats2bfloat162_rn(v2.x, v2.y);
    dst[2 * i + 5] = __floats2bfloat162_rn(v2.z, v2.w);
    dst[2 * i + 6] = __floats2bfloat162_rn(v3.x, v3.y);
    dst[2 * i + 7] = __floats2bfloat162_rn(v3.z, v3.w);
}

// ---------------------------------------------------------------------------
// Helpers
// ---------------------------------------------------------------------------
__device__ __forceinline__ void cp_async16(uint32_t smem_addr, const void* gptr) {
    asm volatile("cp.async.cg.shared.global [%0], [%1], 16;\n"
                 :: "r"(smem_addr), "l"(gptr));
}
__device__ __forceinline__ void cp_commit() { asm volatile("cp.async.commit_group;\n"); }
template <int N> __device__ __forceinline__ void cp_wait() {
    asm volatile("cp.async.wait_group %0;\n" :: "n"(N));
}

__device__ __forceinline__ void mma16816(float* d, const uint32_t* a, uint32_t b0, uint32_t b1) {
    asm volatile(
        "mma.sync.aligned.m16n8k16.row.col.f32.bf16.bf16.f32 "
        "{%0,%1,%2,%3}, {%4,%5,%6,%7}, {%8,%9}, {%0,%1,%2,%3};\n"
        : "+f"(d[0]), "+f"(d[1]), "+f"(d[2]), "+f"(d[3])
        : "r"(a[0]), "r"(a[1]), "r"(a[2]), "r"(a[3]), "r"(b0), "r"(b1));
}

// ---------------------------------------------------------------------------
// Kernel 2: tiled bf16 MMA + per-identity-block min/max reduction (R4 body).
// grid (MTILES, NSPLIT) = 1024 CTAs, 256 threads, 2 CTAs/SM.
// BPS=8 iters/CTA -> near-perfect SM balance; prologue cheapened:
// A staged via cp.async from pre-converted g_f_bf (group-ordered before B0).
// ---------------------------------------------------------------------------
extern __shared__ char smem_raw[];

__global__ __launch_bounds__(256, 2) void k_main() {
    __nv_bfloat16* sA = (__nv_bfloat16*)smem_raw;                  // MTILE x SROW
    __nv_bfloat16* sB = sA + MTILE * SROW;                         // 2 x BLKC x SROW
    float* sMax = (float*)(sB + 2 * BLKC * SROW);                  // MTILE x 2
    float* sMin = sMax + MTILE * 2;                                // MTILE x 2

    const int tid  = threadIdx.x;
    const int wid  = tid >> 5;
    const int lane = tid & 31;
    const int wm   = wid & 3;       // warp row (0..3)
    const int wn   = wid >> 2;      // warp col (0..1)
    const int g    = lane >> 2;
    const int q    = lane & 3;
    const int m0   = blockIdx.x * MTILE;
    const int split = blockIdx.y;
    const int jbase = split * BPS;

    // Stage a 128x128 bf16 tile from gsrc into 16B-chunked SROW layout
    auto stage = [&](const __nv_bfloat16* gsrc, __nv_bfloat16* dstb) {
        const char* src = (const char*)gsrc;
        #pragma unroll
        for (int it = 0; it < 8; it++) {
            int idx = tid + it * 256;                // 0..2047
            int r = idx >> 4, ch = idx & 15;
            uint32_t da = (uint32_t)__cvta_generic_to_shared(dstb + r * SROW + ch * 8);
            cp_async16(da, src + (size_t)idx * 16);
        }
        cp_commit();
    };
    // Group order: A first, then B0 (wait<1> later = A done, B0 may fly)
    stage(g_f_bf + (size_t)m0 * CDIM, sA);
    stage(g_fs_bf + (size_t)jbase * BLKC * CDIM, sB);

    cp_wait<1>();          // A resident (B0 may still be in flight)
    __syncthreads();

    // Preload A fragments: 32 rows x K=128 per warp (64 regs)
    uint32_t afr[2][8][4];
    {
        const int row_off = lane & 15;
        const int col_off = 8 * (lane >> 4);
#pragma unroll
        for (int mi = 0; mi < 2; mi++) {
            const int rm = 32 * wm + 16 * mi + row_off;
#pragma unroll
            for (int ks = 0; ks < 8; ks++) {
                uint32_t addr = (uint32_t)__cvta_generic_to_shared(&sA[rm * SROW + 16 * ks + col_off]);
                asm volatile("ldmatrix.sync.aligned.m8n8.x4.shared.b16 {%0,%1,%2,%3}, [%4];"
                             : "=r"(afr[mi][ks][0]), "=r"(afr[mi][ks][1]),
                               "=r"(afr[mi][ks][2]), "=r"(afr[mi][ks][3])
                             : "r"(addr));
            }
        }
    }

    // B fragment offsets (bf16 elements): conflict-free (word = 4g+q mod 32)
    uint32_t boff[8];
#pragma unroll
    for (int ni = 0; ni < 8; ni++)
        boff[ni] = (uint32_t)((64 * wn + 8 * ni + g) * SROW + 2 * q);

    float negacc = 0.0f;
    float posval = 0.0f;

    for (int jb = 0; jb < BPS; ++jb) {
        const int buf = jb & 1;
        if (jb + 1 < BPS) {
            stage(g_fs_bf + (size_t)(jbase + jb + 1) * BLKC * CDIM, sB + (buf ^ 1) * BLKC * SROW);
            cp_wait<1>();
        } else {
            cp_wait<0>();
        }
        __syncthreads();

        const __nv_bfloat16* bbase = sB + buf * BLKC * SROW;

        float vmx[2][2], vmn[2][2];
#pragma unroll
        for (int p = 0; p < 2; p++) {          // two 64-col N passes (reg pressure)
            float acc[2][4][4];
#pragma unroll
            for (int mi = 0; mi < 2; mi++)
#pragma unroll
                for (int n4 = 0; n4 < 4; n4++)
#pragma unroll
                    for (int cc = 0; cc < 4; cc++) acc[mi][n4][cc] = 0.0f;

#pragma unroll
            for (int ks = 0; ks < 8; ks++) {
                const int kc = 16 * ks;
#pragma unroll
                for (int n4 = 0; n4 < 4; n4++) {
                    const __nv_bfloat16* bp = bbase + boff[4 * p + n4];
                    uint32_t b0 = *(const uint32_t*)(bp + kc);
                    uint32_t b1 = *(const uint32_t*)(bp + kc + 8);
                    mma16816(acc[0][n4], afr[0][ks], b0, b1);
                    mma16816(acc[1][n4], afr[1][ks], b0, b1);
                }
            }
            // fold this pass's 8 col-values per row into running partials
#pragma unroll
            for (int mi = 0; mi < 2; mi++) {
#pragma unroll
                for (int h = 0; h < 2; h++) {
                    float mx = -1e30f, mn = 1e30f;
#pragma unroll
                    for (int n4 = 0; n4 < 4; n4++) {
                        float c0 = acc[mi][n4][2 * h];
                        float c1 = acc[mi][n4][2 * h + 1];
                        mx = fmaxf(mx, fmaxf(c0, c1));
                        mn = fminf(mn, fminf(c0, c1));
                    }
                    if (p == 0) { vmx[mi][h] = mx; vmn[mi][h] = mn; }
                    else { vmx[mi][h] = fmaxf(vmx[mi][h], mx); vmn[mi][h] = fminf(vmn[mi][h], mn); }
                }
            }
        }

        // cross-lane (q) reduce + smem
#pragma unroll
        for (int mi = 0; mi < 2; mi++) {
#pragma unroll
            for (int h = 0; h < 2; h++) {
                float mx = vmx[mi][h], mn = vmn[mi][h];
                mx = fmaxf(mx, __shfl_xor_sync(0xFFFFFFFFu, mx, 1));
                mx = fmaxf(mx, __shfl_xor_sync(0xFFFFFFFFu, mx, 2));
                mn = fminf(mn, __shfl_xor_sync(0xFFFFFFFFu, mn, 1));
                mn = fminf(mn, __shfl_xor_sync(0xFFFFFFFFu, mn, 2));
                if (q == 0) {
                    int row = 32 * wm + 16 * mi + 8 * h + g;
                    sMax[row * 2 + wn] = mx;
                    sMin[row * 2 + wn] = mn;
                }
            }
        }
        __syncthreads();

        if (tid < MTILE) {
            float mx = fmaxf(sMax[tid * 2], sMax[tid * 2 + 1]);
            float mn = fminf(sMin[tid * 2], sMin[tid * 2 + 1]);
            int anchor = m0 + tid;
            if ((anchor >> 4) == (jbase + jb))       // own identity block
                posval = expf(mn * INV_TEMP);        // min of exp == exp of min
            else
                negacc += expf(mx * INV_TEMP);       // max of exp == exp of max
        }
        // next iter's wait+syncthreads orders sMax reads vs. rewrites
    }

    if (tid < MTILE) {
        g_negpart[split * BSZ + m0 + tid] = negacc;
        g_pospart[split * BSZ + m0 + tid] = posval;
    }
}

// ---------------------------------------------------------------------------
// Kernel 3a: per-anchor loss + per-CTA partial sum (32 CTAs x 128 threads)
// ---------------------------------------------------------------------------
__global__ void k_final_a() {
    __shared__ double red[128];
    const int tid = threadIdx.x;
    const int a = blockIdx.x * 128 + tid;
    float neg = 0.0f, pos = 0.0f;
#pragma unroll
    for (int sp = 0; sp < NSPLIT; sp++) {
        neg += g_negpart[sp * BSZ + a];
        pos += g_pospart[sp * BSZ + a];
    }
    float loss = -logf(pos / (pos + neg + EPSV) + EPSV);
    red[tid] = (double)loss;
    __syncthreads();
    for (int o = 64; o > 0; o >>= 1) {
        if (tid < o) red[tid] += red[tid + o];
        __syncthreads();
    }
    if (tid == 0) g_losspart[blockIdx.x] = red[0];
}

// ---------------------------------------------------------------------------
// Kernel 3b: combine 32 partials -> mean (lane-parallel, deterministic tree)
// ---------------------------------------------------------------------------
__global__ void k_final_b(float* __restrict__ out) {
    const int lane = threadIdx.x;
    double s = g_losspart[lane];
    // fixed binary tree via shuffles on the double's two words
#pragma unroll
    for (int o = 16; o > 0; o >>= 1) {
        unsigned lo = __shfl_down_sync(0xFFFFFFFFu, (unsigned)(__double_as_longlong(s) & 0xFFFFFFFFull), o);
        unsigned hi = __shfl_down_sync(0xFFFFFFFFu, (unsigned)((unsigned long long)__double_as_longlong(s) >> 32), o);
        double other = __longlong_as_double(((unsigned long long)hi << 32) | lo);
        s += other;
    }
    if (lane == 0) out[0] = (float)(s / (double)BSZ);
}

// ---------------------------------------------------------------------------
// Launch
// ---------------------------------------------------------------------------
extern "C" void kernel_launch(void* const* d_in, const int* in_sizes, int n_in,
                              void* d_out, int out_size) {
    const float* feats   = (const float*)d_in[0];   // [4096,128] fp32
    const float* feats_s = (const float*)d_in[1];   // [4096,8,128] fp32
    float* out = (float*)d_out;

    // A (34816) + 2xB (69632) + reduce scratch (2048) = 106496 B; 2 CTAs/SM
    const int smem_bytes = MTILE * SROW * 2 + 2 * BLKC * SROW * 2 + MTILE * 2 * 4 * 2;
    cudaFuncSetAttribute(k_main, cudaFuncAttributeMaxDynamicSharedMemorySize, smem_bytes);

    // (NSUP + BSZ) * CDIM / 16 threads = 294912 -> 1152 blocks of 256
    k_convert<<<((NSUP + BSZ) * CDIM / 16) / 256, 256>>>(feats_s, feats);
    dim3 grid(MTILES, NSPLIT);
    k_main<<<grid, 256, smem_bytes>>>();
    k_final_a<<<32, 128>>>();
    k_final_b<<<1, 32>>>(out);
}